// round 7
// baseline (speedup 1.0000x reference)
#include <cuda_runtime.h>
#include <cuda_bf16.h>
#include <math.h>
#include <stdint.h>

// Problem constants
#define BB   4
#define TT   3072
#define DD   1024
#define HH   16
#define HDIM 64
#define TKK  1025   // 1 + 3072/3

// -------- scratch (no cudaMalloc allowed) --------
__device__ float g_wt  [1024 * 3072];
__device__ float g_ktmp[BB * TKK * DD];
__device__ float g_q   [BB * TT  * DD];
__device__ float g_k   [BB * TKK * DD];
__device__ float g_v   [BB * TKK * DD];
__device__ float g_att [BB * TT  * DD];

static __device__ __forceinline__ uint32_t smem_u32(const void* p) {
    uint32_t a;
    asm("{ .reg .u64 t; cvta.to.shared.u64 t, %1; cvt.u32.u64 %0, t; }"
        : "=r"(a) : "l"(p));
    return a;
}

static __device__ __forceinline__ void mma16816(
    float* d, const uint32_t* a, uint32_t b0, uint32_t b1)
{
    asm volatile(
        "mma.sync.aligned.m16n8k16.row.col.f32.bf16.bf16.f32 "
        "{%0,%1,%2,%3}, {%4,%5,%6,%7}, {%8,%9}, {%0,%1,%2,%3};"
        : "+f"(d[0]), "+f"(d[1]), "+f"(d[2]), "+f"(d[3])
        : "r"(a[0]), "r"(a[1]), "r"(a[2]), "r"(a[3]), "r"(b0), "r"(b1));
}

static __device__ __forceinline__ void ldm4(uint32_t* r, uint32_t addr) {
    asm volatile(
        "ldmatrix.sync.aligned.m8n8.x4.shared.b16 {%0,%1,%2,%3}, [%4];"
        : "=r"(r[0]), "=r"(r[1]), "=r"(r[2]), "=r"(r[3]) : "r"(addr));
}

static __device__ __forceinline__ void ldm4t(uint32_t* r, uint32_t addr) {
    asm volatile(
        "ldmatrix.sync.aligned.m8n8.x4.trans.shared.b16 {%0,%1,%2,%3}, [%4];"
        : "=r"(r[0]), "=r"(r[1]), "=r"(r[2]), "=r"(r[3]) : "r"(addr));
}

static __device__ __forceinline__ uint32_t packbf2(float x, float y) {
    __nv_bfloat162 t = __floats2bfloat162_rn(x, y);
    return *(uint32_t*)&t;
}

static __device__ __forceinline__ void split8(float4 a, float4 b, uint4& hi, uint4& lo) {
    float f[8] = {a.x, a.y, a.z, a.w, b.x, b.y, b.z, b.w};
    float r[8];
#pragma unroll
    for (int i = 0; i < 8; i++) {
        __nv_bfloat16 h = __float2bfloat16_rn(f[i]);
        r[i] = f[i] - __bfloat162float(h);
    }
    hi.x = packbf2(f[0], f[1]); hi.y = packbf2(f[2], f[3]);
    hi.z = packbf2(f[4], f[5]); hi.w = packbf2(f[6], f[7]);
    lo.x = packbf2(r[0], r[1]); lo.y = packbf2(r[2], r[3]);
    lo.z = packbf2(r[4], r[5]); lo.w = packbf2(r[6], r[7]);
}

static __device__ __forceinline__ void split2(float a, float b, uint32_t& hi, uint32_t& lo) {
    __nv_bfloat16 ha = __float2bfloat16_rn(a);
    __nv_bfloat16 hb = __float2bfloat16_rn(b);
    hi = ((uint32_t)__bfloat16_as_ushort(hb) << 16) | (uint32_t)__bfloat16_as_ushort(ha);
    lo = packbf2(a - __bfloat162float(ha), b - __bfloat162float(hb));
}

// ================= misc prep kernels =================
__global__ void conv_w_transpose(const float* __restrict__ W, float* __restrict__ out) {
    int idx = blockIdx.x * 256 + threadIdx.x;
    if (idx < 1024 * 1024 * 3) {
        int kw = idx % 3;
        int i  = (idx / 3) & 1023;
        int o  = idx / 3072;
        out[o * 3072 + kw * 1024 + i] = W[idx];
    }
}

__global__ void copy_first_rows(const float* __restrict__ x, float* __restrict__ ktmp) {
    int idx = blockIdx.x * 256 + threadIdx.x;
    int b = idx >> 10, d = idx & 1023;
    ktmp[(size_t)b * TKK * DD + d] = x[(size_t)b * TT * DD + d];
}

// ================================================================
// GEMM via mma.sync bf16-split.
// Tile 128(M) x 64(N), K chunk 64. 256 threads = 8 warps (4m x 2n),
// warp tile 32x32. Single smem stage (55.3KB) -> 2 CTAs/SM;
// cross-CTA overlap hides LDG/STS/sync bubbles.
// ================================================================
#define GPITCH 144
#define GT_AHI 0
#define GT_ALO (128 * GPITCH)
#define GT_BHI (2 * 128 * GPITCH)
#define GT_BLO (2 * 128 * GPITCH + 64 * GPITCH)
#define G_SMEM (2 * 128 * GPITCH + 2 * 64 * GPITCH)   // 55296

template <int OUT_MODE, bool HAS_BIAS>
__global__ void __launch_bounds__(256, 2)
mma_gemm(const float* __restrict__ A, const float* __restrict__ W,
         const float* __restrict__ bias, float* __restrict__ C,
         int M, int N, int K) {
    extern __shared__ __align__(16) char smem[];
    const uint32_t sb = smem_u32(smem);

    const int tid  = threadIdx.x;
    const int lane = tid & 31;
    const int warp = tid >> 5;
    const int wm   = warp >> 1;     // 0..3
    const int wn   = warp & 1;      // 0..1
    const int bm   = blockIdx.y * 128;
    const int bn   = blockIdx.x * 64;

    // load mapping: A 4 slots (128 rows x 8 pair-cols), B 2 slots (64 rows)
    int rowA[4], kcA[4], rowB[2], kcB[2];
#pragma unroll
    for (int s = 0; s < 4; s++) {
        int p = s * 256 + tid;
        rowA[s] = p >> 3;
        kcA[s]  = (p & 7) * 8;
    }
#pragma unroll
    for (int s = 0; s < 2; s++) {
        int p = s * 256 + tid;
        rowB[s] = p >> 3;
        kcB[s]  = (p & 7) * 8;
    }

    uint32_t aoff[2], boff[2];
#pragma unroll
    for (int mi = 0; mi < 2; mi++) {
        int rA = wm * 32 + mi * 16 + (lane & 15);
        aoff[mi] = (uint32_t)(rA * GPITCH + ((lane >> 4) * 8) * 2);
    }
#pragma unroll
    for (int pi = 0; pi < 2; pi++) {
        int rB = wn * 32 + pi * 16 + ((lane >> 4) << 3) + (lane & 7);
        boff[pi] = (uint32_t)(rB * GPITCH + (((lane >> 3) & 1) * 8) * 2);
    }

    float acc[2][4][4];
#pragma unroll
    for (int mi = 0; mi < 2; mi++)
#pragma unroll
        for (int ni = 0; ni < 4; ni++)
#pragma unroll
            for (int t = 0; t < 4; t++) acc[mi][ni][t] = 0.f;

    const int nc = K >> 6;

    for (int c = 0; c < nc; c++) {
        if (c) __syncthreads();
        const int kb = c << 6;
        // ---- LDG (batched) ----
        float4 av[4][2], bv[2][2];
#pragma unroll
        for (int s = 0; s < 4; s++) {
            int ar = bm + rowA[s]; ar = ar < M ? ar : M - 1;
            const float* pa = A + (size_t)ar * K + kb + kcA[s];
            av[s][0] = *(const float4*)pa;
            av[s][1] = *(const float4*)(pa + 4);
        }
#pragma unroll
        for (int s = 0; s < 2; s++) {
            const float* pb = W + (size_t)(bn + rowB[s]) * K + kb + kcB[s];
            bv[s][0] = *(const float4*)pb;
            bv[s][1] = *(const float4*)(pb + 4);
        }
        // ---- convert + STS ----
#pragma unroll
        for (int s = 0; s < 4; s++) {
            const uint32_t off = (uint32_t)(rowA[s] * GPITCH + kcA[s] * 2);
            uint4 h, l;
            split8(av[s][0], av[s][1], h, l);
            *(uint4*)(smem + GT_AHI + off) = h;
            *(uint4*)(smem + GT_ALO + off) = l;
        }
#pragma unroll
        for (int s = 0; s < 2; s++) {
            const uint32_t off = (uint32_t)(rowB[s] * GPITCH + kcB[s] * 2);
            uint4 h, l;
            split8(bv[s][0], bv[s][1], h, l);
            *(uint4*)(smem + GT_BHI + off) = h;
            *(uint4*)(smem + GT_BLO + off) = l;
        }
        __syncthreads();

        // ---- MMA over 4 k16 steps ----
#pragma unroll
        for (int kk = 0; kk < 4; kk++) {
            const uint32_t ko = (uint32_t)(kk * 32);
            uint32_t ah[2][4], al[2][4], bh[2][4], bl[2][4];
            ldm4(ah[0], sb + GT_AHI + aoff[0] + ko);
            ldm4(ah[1], sb + GT_AHI + aoff[1] + ko);
            ldm4(bh[0], sb + GT_BHI + boff[0] + ko);
            ldm4(bh[1], sb + GT_BHI + boff[1] + ko);
            ldm4(al[0], sb + GT_ALO + aoff[0] + ko);
            ldm4(al[1], sb + GT_ALO + aoff[1] + ko);
            ldm4(bl[0], sb + GT_BLO + boff[0] + ko);
            ldm4(bl[1], sb + GT_BLO + boff[1] + ko);
#pragma unroll
            for (int mi = 0; mi < 2; mi++)
#pragma unroll
                for (int ni = 0; ni < 4; ni++) {
                    const int pr = ni >> 1, ix = (ni & 1) * 2;
                    mma16816(acc[mi][ni], ah[mi], bh[pr][ix], bh[pr][ix + 1]);
                    mma16816(acc[mi][ni], ah[mi], bl[pr][ix], bl[pr][ix + 1]);
                    mma16816(acc[mi][ni], al[mi], bh[pr][ix], bh[pr][ix + 1]);
                }
        }
    }

    // epilogue
#pragma unroll
    for (int mi = 0; mi < 2; mi++) {
#pragma unroll
        for (int ni = 0; ni < 4; ni++) {
            const int col = bn + wn * 32 + ni * 8 + (lane & 3) * 2;
            float2 v0 = make_float2(acc[mi][ni][0], acc[mi][ni][1]);
            float2 v1 = make_float2(acc[mi][ni][2], acc[mi][ni][3]);
            if (HAS_BIAS) {
                const float bx = bias[col], by = bias[col + 1];
                v0.x += bx; v0.y += by; v1.x += bx; v1.y += by;
            }
            const int r0 = bm + wm * 32 + mi * 16 + (lane >> 2);
            const int r1 = r0 + 8;
            if (r0 < M) {
                size_t rb;
                if (OUT_MODE == 1) {
                    const int b = r0 >> 10, rr = r0 & 1023;
                    rb = ((size_t)b * TKK + 1 + rr) * (size_t)N;
                } else rb = (size_t)r0 * (size_t)N;
                *(float2*)&C[rb + col] = v0;
            }
            if (r1 < M) {
                size_t rb;
                if (OUT_MODE == 1) {
                    const int b = r1 >> 10, rr = r1 & 1023;
                    rb = ((size_t)b * TKK + 1 + rr) * (size_t)N;
                } else rb = (size_t)r1 * (size_t)N;
                *(float2*)&C[rb + col] = v1;
            }
        }
    }
}

// ================================================================
// Flash attention via mma.sync bf16-split (round-5 proven, unchanged)
// ================================================================
#define APITCH 144
#define A_SKH 0
#define A_SKL (64 * APITCH)
#define A_SVH (2 * 64 * APITCH)
#define A_SVL (3 * 64 * APITCH)

__global__ void __launch_bounds__(256)
attn_mma(const float* __restrict__ Qg, const float* __restrict__ Kg,
         const float* __restrict__ Vg, float* __restrict__ Og) {
    __shared__ __align__(16) char sm[4 * 64 * APITCH];
    const uint32_t sb = smem_u32(sm);

    const int tid  = threadIdx.x;
    const int lane = tid & 31;
    const int w    = tid >> 5;
    const int b    = blockIdx.y >> 4;
    const int h    = blockIdx.y & 15;
    const int q0   = blockIdx.x * 128;

    const float* Qb = Qg + (size_t)b * TT  * DD + h * HDIM;
    const float* Kb = Kg + (size_t)b * TKK * DD + h * HDIM;
    const float* Vb = Vg + (size_t)b * TKK * DD + h * HDIM;

    {
        const int row = tid >> 1;
        const int seg = (tid & 1) * 32;
        const float* pq = Qb + (size_t)(q0 + row) * DD + seg;
        const uint32_t bhi = (row < 64) ? A_SKH : A_SVH;
        const uint32_t blo = (row < 64) ? A_SKL : A_SVL;
        const uint32_t ro  = (uint32_t)((row & 63) * APITCH);
#pragma unroll
        for (int p = 0; p < 4; p++) {
            float4 x0 = ((const float4*)pq)[p * 2];
            float4 x1 = ((const float4*)pq)[p * 2 + 1];
            uint4 hh, ll;
            split8(x0, x1, hh, ll);
            *(uint4*)(sm + bhi + ro + (seg + p * 8) * 2) = hh;
            *(uint4*)(sm + blo + ro + (seg + p * 8) * 2) = ll;
        }
    }
    __syncthreads();

    uint32_t qfh[4][4], qfl[4][4];
    {
        const uint32_t bhi = (w < 4) ? A_SKH : A_SVH;
        const uint32_t blo = (w < 4) ? A_SKL : A_SVL;
        const uint32_t ao = (uint32_t)(((w * 16 + (lane & 15)) & 63) * APITCH
                                       + (lane >> 4) * 16);
#pragma unroll
        for (int ks = 0; ks < 4; ks++) {
            ldm4(qfh[ks], sb + bhi + ao + ks * 32);
            ldm4(qfl[ks], sb + blo + ao + ks * 32);
        }
    }

    float oacc[8][4];
#pragma unroll
    for (int nt = 0; nt < 8; nt++)
#pragma unroll
        for (int t = 0; t < 4; t++) oacc[nt][t] = 0.f;
    float m0 = -1e30f, m1 = -1e30f, l0 = 0.f, l1 = 0.f;

    const int nkb = ((q0 + 127) / 3) / 64 + 1;

    const uint32_t kfo = (uint32_t)((((lane >> 4) << 3) + (lane & 7)) * APITCH
                                    + ((lane >> 3) & 1) * 16);
    const uint32_t vfo = (uint32_t)(((((lane >> 3) & 1) * 8) + (lane & 7)) * APITCH
                                    + ((lane >> 4) & 1) * 16);
    const int rq = lane >> 2;
    const int cq = (lane & 3) * 2;
    const int qg0 = q0 + w * 16 + rq;
    const int qg1 = qg0 + 8;

    for (int kb = 0; kb < nkb; kb++) {
        __syncthreads();
        const int kbase = kb * 64;
        {
            const int row = tid >> 2;
            const int seg = (tid & 3) * 16;
            const float* pk = Kb + (size_t)(kbase + row) * DD + seg;
            const float* pv = Vb + (size_t)(kbase + row) * DD + seg;
            const uint32_t ro = (uint32_t)(row * APITCH + seg * 2);
#pragma unroll
            for (int p = 0; p < 2; p++) {
                float4 x0 = ((const float4*)pk)[p * 2];
                float4 x1 = ((const float4*)pk)[p * 2 + 1];
                uint4 hh, ll;
                split8(x0, x1, hh, ll);
                *(uint4*)(sm + A_SKH + ro + p * 16) = hh;
                *(uint4*)(sm + A_SKL + ro + p * 16) = ll;
                float4 y0 = ((const float4*)pv)[p * 2];
                float4 y1 = ((const float4*)pv)[p * 2 + 1];
                split8(y0, y1, hh, ll);
                *(uint4*)(sm + A_SVH + ro + p * 16) = hh;
                *(uint4*)(sm + A_SVL + ro + p * 16) = ll;
            }
        }
        __syncthreads();

        float sacc[8][4];
#pragma unroll
        for (int nt = 0; nt < 8; nt++)
#pragma unroll
            for (int t = 0; t < 4; t++) sacc[nt][t] = 0.f;

#pragma unroll
        for (int ks = 0; ks < 4; ks++) {
#pragma unroll
            for (int pi = 0; pi < 4; pi++) {
                uint32_t kh[4], kl[4];
                const uint32_t base = (uint32_t)(pi * 16 * APITCH) + kfo + ks * 32;
                ldm4(kh, sb + A_SKH + base);
                ldm4(kl, sb + A_SKL + base);
                mma16816(sacc[2 * pi],     qfh[ks], kh[0], kh[1]);
                mma16816(sacc[2 * pi],     qfh[ks], kl[0], kl[1]);
                mma16816(sacc[2 * pi],     qfl[ks], kh[0], kh[1]);
                mma16816(sacc[2 * pi + 1], qfh[ks], kh[2], kh[3]);
                mma16816(sacc[2 * pi + 1], qfh[ks], kl[2], kl[3]);
                mma16816(sacc[2 * pi + 1], qfl[ks], kh[2], kh[3]);
            }
        }

        float tm0 = -1e30f, tm1 = -1e30f;
#pragma unroll
        for (int nt = 0; nt < 8; nt++) {
            const int kg0 = kbase + nt * 8 + cq;
            const int kg1 = kg0 + 1;
            float s00 = (3 * kg0 <= qg0) ? sacc[nt][0] * 0.125f : -1e30f;
            float s01 = (3 * kg1 <= qg0) ? sacc[nt][1] * 0.125f : -1e30f;
            float s10 = (3 * kg0 <= qg1) ? sacc[nt][2] * 0.125f : -1e30f;
            float s11 = (3 * kg1 <= qg1) ? sacc[nt][3] * 0.125f : -1e30f;
            sacc[nt][0] = s00; sacc[nt][1] = s01;
            sacc[nt][2] = s10; sacc[nt][3] = s11;
            tm0 = fmaxf(tm0, fmaxf(s00, s01));
            tm1 = fmaxf(tm1, fmaxf(s10, s11));
        }
        tm0 = fmaxf(tm0, __shfl_xor_sync(0xffffffffu, tm0, 1));
        tm0 = fmaxf(tm0, __shfl_xor_sync(0xffffffffu, tm0, 2));
        tm1 = fmaxf(tm1, __shfl_xor_sync(0xffffffffu, tm1, 1));
        tm1 = fmaxf(tm1, __shfl_xor_sync(0xffffffffu, tm1, 2));

        const float mn0 = fmaxf(m0, tm0);
        const float mn1 = fmaxf(m1, tm1);
        const float al0 = __expf(m0 - mn0);
        const float al1 = __expf(m1 - mn1);
        float ps0 = 0.f, ps1 = 0.f;
#pragma unroll
        for (int nt = 0; nt < 8; nt++) {
            float p00 = __expf(sacc[nt][0] - mn0);
            float p01 = __expf(sacc[nt][1] - mn0);
            float p10 = __expf(sacc[nt][2] - mn1);
            float p11 = __expf(sacc[nt][3] - mn1);
            sacc[nt][0] = p00; sacc[nt][1] = p01;
            sacc[nt][2] = p10; sacc[nt][3] = p11;
            ps0 += p00 + p01;
            ps1 += p10 + p11;
        }
        ps0 += __shfl_xor_sync(0xffffffffu, ps0, 1);
        ps0 += __shfl_xor_sync(0xffffffffu, ps0, 2);
        ps1 += __shfl_xor_sync(0xffffffffu, ps1, 1);
        ps1 += __shfl_xor_sync(0xffffffffu, ps1, 2);
        l0 = l0 * al0 + ps0;
        l1 = l1 * al1 + ps1;
        m0 = mn0; m1 = mn1;

#pragma unroll
        for (int nt = 0; nt < 8; nt++) {
            oacc[nt][0] *= al0; oacc[nt][1] *= al0;
            oacc[nt][2] *= al1; oacc[nt][3] *= al1;
        }

#pragma unroll
        for (int ks = 0; ks < 4; ks++) {
            uint32_t pah[4], pal[4];
            split2(sacc[2 * ks][0],     sacc[2 * ks][1],     pah[0], pal[0]);
            split2(sacc[2 * ks][2],     sacc[2 * ks][3],     pah[1], pal[1]);
            split2(sacc[2 * ks + 1][0], sacc[2 * ks + 1][1], pah[2], pal[2]);
            split2(sacc[2 * ks + 1][2], sacc[2 * ks + 1][3], pah[3], pal[3]);
#pragma unroll
            for (int di = 0; di < 4; di++) {
                uint32_t vh[4], vl[4];
                const uint32_t base = (uint32_t)(ks * 16 * APITCH) + vfo + di * 32;
                ldm4t(vh, sb + A_SVH + base);
                ldm4t(vl, sb + A_SVL + base);
                mma16816(oacc[2 * di],     pah, vh[0], vh[1]);
                mma16816(oacc[2 * di],     pah, vl[0], vl[1]);
                mma16816(oacc[2 * di],     pal, vh[0], vh[1]);
                mma16816(oacc[2 * di + 1], pah, vh[2], vh[3]);
                mma16816(oacc[2 * di + 1], pah, vl[2], vl[3]);
                mma16816(oacc[2 * di + 1], pal, vh[2], vh[3]);
            }
        }
    }

    const float il0 = 1.0f / l0;
    const float il1 = 1.0f / l1;
    float* po = Og + ((size_t)b * TT + qg0) * DD + h * HDIM;
#pragma unroll
    for (int nt = 0; nt < 8; nt++) {
        const int col = nt * 8 + cq;
        *(float2*)(po + col) =
            make_float2(oacc[nt][0] * il0, oacc[nt][1] * il0);
        *(float2*)(po + (size_t)8 * DD + col) =
            make_float2(oacc[nt][2] * il1, oacc[nt][3] * il1);
    }
}

// ------------------------------------------------------------------
extern "C" void kernel_launch(void* const* d_in, const int* in_sizes, int n_in,
                              void* d_out, int out_size) {
    const float* x     = (const float*)d_in[0];
    const float* Wq    = (const float*)d_in[1];
    const float* Wk    = (const float*)d_in[2];
    const float* Wv    = (const float*)d_in[3];
    const float* Wo    = (const float*)d_in[4];
    const float* bo    = (const float*)d_in[5];
    const float* Wconv = (const float*)d_in[6];
    float* out = (float*)d_out;

    float *wt, *ktmp, *q, *k, *v, *att;
    cudaGetSymbolAddress((void**)&wt,   g_wt);
    cudaGetSymbolAddress((void**)&ktmp, g_ktmp);
    cudaGetSymbolAddress((void**)&q,    g_q);
    cudaGetSymbolAddress((void**)&k,    g_k);
    cudaGetSymbolAddress((void**)&v,    g_v);
    cudaGetSymbolAddress((void**)&att,  g_att);

    cudaFuncSetAttribute(mma_gemm<0, false>,
                         cudaFuncAttributeMaxDynamicSharedMemorySize, G_SMEM);
    cudaFuncSetAttribute(mma_gemm<1, false>,
                         cudaFuncAttributeMaxDynamicSharedMemorySize, G_SMEM);
    cudaFuncSetAttribute(mma_gemm<0, true>,
                         cudaFuncAttributeMaxDynamicSharedMemorySize, G_SMEM);

    conv_w_transpose<<<(1024 * 1024 * 3 + 255) / 256, 256>>>(Wconv, wt);
    copy_first_rows<<<16, 256>>>(x, ktmp);
    mma_gemm<1, false><<<dim3(16, 32), 256, G_SMEM>>>(x, wt, nullptr, ktmp, 4096, 1024, 3072);
    mma_gemm<0, false><<<dim3(16, 96), 256, G_SMEM>>>(x, Wq, nullptr, q, BB * TT, 1024, 1024);
    mma_gemm<0, false><<<dim3(16, 33), 256, G_SMEM>>>(ktmp, Wk, nullptr, k, BB * TKK, 1024, 1024);
    mma_gemm<0, false><<<dim3(16, 33), 256, G_SMEM>>>(ktmp, Wv, nullptr, v, BB * TKK, 1024, 1024);
    attn_mma<<<dim3(24, 64), 256>>>(q, k, v, att);
    mma_gemm<0, true><<<dim3(16, 96), 256, G_SMEM>>>(att, Wo, bo, out, BB * TT, 1024, 1024);
}

// round 8
// speedup vs baseline: 1.0859x; 1.0859x over previous
#include <cuda_runtime.h>
#include <cuda_bf16.h>
#include <math.h>
#include <stdint.h>

// Problem constants
#define BB   4
#define TT   3072
#define DD   1024
#define HH   16
#define HDIM 64
#define TKK  1025   // 1 + 3072/3

#define NX  (BB * TT * DD)     // 12582912
#define NKT (BB * TKK * DD)    // 4198400
#define NW  (DD * DD)          // 1048576
#define NWT (DD * 3 * DD)      // 3145728

// -------- bf16 hi/lo scratch (no cudaMalloc allowed) --------
__device__ __nv_bfloat16 g_xh[NX],  g_xl[NX];
__device__ __nv_bfloat16 g_wqh[NW], g_wql[NW];
__device__ __nv_bfloat16 g_wkh[NW], g_wkl[NW];
__device__ __nv_bfloat16 g_wvh[NW], g_wvl[NW];
__device__ __nv_bfloat16 g_woh[NW], g_wol[NW];
__device__ __nv_bfloat16 g_wth[NWT], g_wtl[NWT];
__device__ __nv_bfloat16 g_kth[NKT], g_ktl[NKT];   // ktmp
__device__ __nv_bfloat16 g_qh[NX],  g_ql[NX];
__device__ __nv_bfloat16 g_kh[NKT], g_kl[NKT];
__device__ __nv_bfloat16 g_vh[NKT], g_vl[NKT];
__device__ __nv_bfloat16 g_ah[NX],  g_al[NX];      // attn out

static __device__ __forceinline__ uint32_t smem_u32(const void* p) {
    uint32_t a;
    asm("{ .reg .u64 t; cvta.to.shared.u64 t, %1; cvt.u32.u64 %0, t; }"
        : "=r"(a) : "l"(p));
    return a;
}

static __device__ __forceinline__ void mma16816(
    float* d, const uint32_t* a, uint32_t b0, uint32_t b1)
{
    asm volatile(
        "mma.sync.aligned.m16n8k16.row.col.f32.bf16.bf16.f32 "
        "{%0,%1,%2,%3}, {%4,%5,%6,%7}, {%8,%9}, {%0,%1,%2,%3};"
        : "+f"(d[0]), "+f"(d[1]), "+f"(d[2]), "+f"(d[3])
        : "r"(a[0]), "r"(a[1]), "r"(a[2]), "r"(a[3]), "r"(b0), "r"(b1));
}

static __device__ __forceinline__ void ldm4(uint32_t* r, uint32_t addr) {
    asm volatile(
        "ldmatrix.sync.aligned.m8n8.x4.shared.b16 {%0,%1,%2,%3}, [%4];"
        : "=r"(r[0]), "=r"(r[1]), "=r"(r[2]), "=r"(r[3]) : "r"(addr));
}

static __device__ __forceinline__ void ldm4t(uint32_t* r, uint32_t addr) {
    asm volatile(
        "ldmatrix.sync.aligned.m8n8.x4.trans.shared.b16 {%0,%1,%2,%3}, [%4];"
        : "=r"(r[0]), "=r"(r[1]), "=r"(r[2]), "=r"(r[3]) : "r"(addr));
}

#define CP16(dst, src) \
    asm volatile("cp.async.cg.shared.global [%0], [%1], 16;" \
                 :: "r"((uint32_t)(dst)), "l"(src) : "memory")
#define CP_COMMIT() asm volatile("cp.async.commit_group;" ::: "memory")
template <int N> static __device__ __forceinline__ void cp_wait() {
    asm volatile("cp.async.wait_group %0;" :: "n"(N) : "memory");
}

static __device__ __forceinline__ uint32_t packbf2(float x, float y) {
    __nv_bfloat162 t = __floats2bfloat162_rn(x, y);
    return *(uint32_t*)&t;
}

static __device__ __forceinline__ void split8(float4 a, float4 b, uint4& hi, uint4& lo) {
    float f[8] = {a.x, a.y, a.z, a.w, b.x, b.y, b.z, b.w};
    float r[8];
#pragma unroll
    for (int i = 0; i < 8; i++) {
        __nv_bfloat16 h = __float2bfloat16_rn(f[i]);
        r[i] = f[i] - __bfloat162float(h);
    }
    hi.x = packbf2(f[0], f[1]); hi.y = packbf2(f[2], f[3]);
    hi.z = packbf2(f[4], f[5]); hi.w = packbf2(f[6], f[7]);
    lo.x = packbf2(r[0], r[1]); lo.y = packbf2(r[2], r[3]);
    lo.z = packbf2(r[4], r[5]); lo.w = packbf2(r[6], r[7]);
}

static __device__ __forceinline__ void split2(float a, float b, uint32_t& hi, uint32_t& lo) {
    __nv_bfloat16 ha = __float2bfloat16_rn(a);
    __nv_bfloat16 hb = __float2bfloat16_rn(b);
    hi = ((uint32_t)__bfloat16_as_ushort(hb) << 16) | (uint32_t)__bfloat16_as_ushort(ha);
    lo = packbf2(a - __bfloat162float(ha), b - __bfloat162float(hb));
}

// ================= prep / conversion kernels =================
__global__ void split8_arr(const float* __restrict__ src,
                           __nv_bfloat16* __restrict__ h,
                           __nv_bfloat16* __restrict__ l, int n) {
    int i = (blockIdx.x * 256 + threadIdx.x) * 8;
    if (i < n) {
        float4 a = *(const float4*)(src + i);
        float4 b = *(const float4*)(src + i + 4);
        uint4 hh, ll;
        split8(a, b, hh, ll);
        *(uint4*)(h + i) = hh;
        *(uint4*)(l + i) = ll;
    }
}

// Wconv (O,I,KW) -> transposed (O,KW,I) hi/lo
__global__ void conv_w_split(const float* __restrict__ W,
                             __nv_bfloat16* __restrict__ h,
                             __nv_bfloat16* __restrict__ l) {
    int idx = blockIdx.x * 256 + threadIdx.x;
    if (idx < NWT) {
        int kw = idx % 3;
        int i  = (idx / 3) & 1023;
        int o  = idx / 3072;
        float f = W[idx];
        __nv_bfloat16 hh = __float2bfloat16_rn(f);
        int dst = o * 3072 + kw * 1024 + i;
        h[dst] = hh;
        l[dst] = __float2bfloat16_rn(f - __bfloat162float(hh));
    }
}

__global__ void first_rows(const __nv_bfloat16* __restrict__ xh,
                           const __nv_bfloat16* __restrict__ xl,
                           __nv_bfloat16* __restrict__ kth,
                           __nv_bfloat16* __restrict__ ktl) {
    int idx = blockIdx.x * 256 + threadIdx.x;   // 4096
    int b = idx >> 10, d = idx & 1023;
    kth[(size_t)b * TKK * DD + d] = xh[(size_t)b * TT * DD + d];
    ktl[(size_t)b * TKK * DD + d] = xl[(size_t)b * TT * DD + d];
}

// ================================================================
// GEMM: C = A * B^T, A/B pre-split bf16 hi/lo. 3-product split MMA.
// Tile 128x128, K chunk 32, 4-stage cp.async ring (issue 2 ahead,
// one sync per chunk). 512 threads = 16 warps (4x4), warp tile 32x32.
// Stage buffers: AHI/ALO/BHI/BLO, 128 rows x 80B pitch (64B data).
// MODE 0: write hi/lo bf16. MODE 1: hi/lo scatter to ktmp rows.
// MODE 2: fp32 + bias.
// ================================================================
#define GPI 80
#define GSTG (4 * 128 * GPI)       // 40960
#define GB_AHI 0
#define GB_ALO (128 * GPI)
#define GB_BHI (2 * 128 * GPI)
#define GB_BLO (3 * 128 * GPI)
#define G_SMEM (4 * GSTG)          // 163840

template <int MODE>
__global__ void __launch_bounds__(512)
mma_gemm(const __nv_bfloat16* __restrict__ Ah, const __nv_bfloat16* __restrict__ Al,
         const __nv_bfloat16* __restrict__ Bh, const __nv_bfloat16* __restrict__ Bl,
         const float* __restrict__ bias,
         void* __restrict__ OutH, void* __restrict__ OutL,
         int M, int N, int K) {
    extern __shared__ __align__(16) char smem[];
    const uint32_t sb = smem_u32(smem);

    const int tid  = threadIdx.x;
    const int lane = tid & 31;
    const int warp = tid >> 5;
    const int wm   = warp >> 2;
    const int wn   = warp & 3;
    const int bm   = blockIdx.y * 128;
    const int bn   = blockIdx.x * 128;

    // cp.async mapping: row = tid>>2 (0..127), quarter = tid&3 (16B each)
    const int crow = tid >> 2;
    const int cq8  = (tid & 3) * 8;          // element offset within chunk
    int arow = bm + crow; if (arow >= M) arow = M - 1;
    const __nv_bfloat16* pAh = Ah + (size_t)arow * K + cq8;
    const __nv_bfloat16* pAl = Al + (size_t)arow * K + cq8;
    const __nv_bfloat16* pBh = Bh + (size_t)(bn + crow) * K + cq8;
    const __nv_bfloat16* pBl = Bl + (size_t)(bn + crow) * K + cq8;
    const uint32_t soff = (uint32_t)(crow * GPI + (tid & 3) * 16);

    // ldmatrix offsets (pitch 80, conflict-free)
    uint32_t aoff[2], boff[2];
#pragma unroll
    for (int mi = 0; mi < 2; mi++) {
        int rA = wm * 32 + mi * 16 + (lane & 15);
        aoff[mi] = (uint32_t)(rA * GPI + (lane >> 4) * 16);
    }
#pragma unroll
    for (int pi = 0; pi < 2; pi++) {
        int rB = wn * 32 + pi * 16 + ((lane >> 4) << 3) + (lane & 7);
        boff[pi] = (uint32_t)(rB * GPI + ((lane >> 3) & 1) * 16);
    }

    float acc[2][4][4];
#pragma unroll
    for (int mi = 0; mi < 2; mi++)
#pragma unroll
        for (int ni = 0; ni < 4; ni++)
#pragma unroll
            for (int t = 0; t < 4; t++) acc[mi][ni][t] = 0.f;

    const int nc = K >> 5;     // chunks of 32

    auto issue = [&](int c) {
        const int kb = c << 5;
        const uint32_t st = sb + (uint32_t)(c & 3) * GSTG + soff;
        CP16(st + GB_AHI, pAh + kb);
        CP16(st + GB_ALO, pAl + kb);
        CP16(st + GB_BHI, pBh + kb);
        CP16(st + GB_BLO, pBl + kb);
    };

    issue(0); CP_COMMIT();
    issue(1); CP_COMMIT();

    for (int c = 0; c < nc; c++) {
        if (c + 2 < nc) {
            issue(c + 2); CP_COMMIT();
            cp_wait<2>();
        } else if (c + 1 < nc) {
            cp_wait<1>();
        } else {
            cp_wait<0>();
        }
        __syncthreads();

        const uint32_t sbc = sb + (uint32_t)(c & 3) * GSTG;
#pragma unroll
        for (int kk = 0; kk < 2; kk++) {
            const uint32_t ko = (uint32_t)(kk * 32);
            uint32_t ah[2][4], al[2][4], bh[2][4], bl[2][4];
            ldm4(ah[0], sbc + GB_AHI + aoff[0] + ko);
            ldm4(ah[1], sbc + GB_AHI + aoff[1] + ko);
            ldm4(bh[0], sbc + GB_BHI + boff[0] + ko);
            ldm4(bh[1], sbc + GB_BHI + boff[1] + ko);
            ldm4(al[0], sbc + GB_ALO + aoff[0] + ko);
            ldm4(al[1], sbc + GB_ALO + aoff[1] + ko);
            ldm4(bl[0], sbc + GB_BLO + boff[0] + ko);
            ldm4(bl[1], sbc + GB_BLO + boff[1] + ko);
#pragma unroll
            for (int mi = 0; mi < 2; mi++)
#pragma unroll
                for (int ni = 0; ni < 4; ni++) {
                    const int pr = ni >> 1, ix = (ni & 1) * 2;
                    mma16816(acc[mi][ni], ah[mi], bh[pr][ix], bh[pr][ix + 1]);
                    mma16816(acc[mi][ni], ah[mi], bl[pr][ix], bl[pr][ix + 1]);
                    mma16816(acc[mi][ni], al[mi], bh[pr][ix], bh[pr][ix + 1]);
                }
        }
    }

    // epilogue
#pragma unroll
    for (int mi = 0; mi < 2; mi++) {
#pragma unroll
        for (int ni = 0; ni < 4; ni++) {
            const int col = bn + wn * 32 + ni * 8 + (lane & 3) * 2;
            const int r0 = bm + wm * 32 + mi * 16 + (lane >> 2);
            const int r1 = r0 + 8;
#pragma unroll
            for (int half = 0; half < 2; half++) {
                const int rr = half ? r1 : r0;
                if (rr >= M) continue;
                float va = acc[mi][ni][half * 2 + 0];
                float vb = acc[mi][ni][half * 2 + 1];
                size_t rb;
                if (MODE == 1) {
                    const int bb = rr >> 10, r2 = rr & 1023;
                    rb = ((size_t)bb * TKK + 1 + r2) * (size_t)N;
                } else {
                    rb = (size_t)rr * (size_t)N;
                }
                if (MODE == 2) {
                    float* C = (float*)OutH;
                    *(float2*)&C[rb + col] =
                        make_float2(va + bias[col], vb + bias[col + 1]);
                } else {
                    __nv_bfloat16* Ch = (__nv_bfloat16*)OutH;
                    __nv_bfloat16* Cl = (__nv_bfloat16*)OutL;
                    uint32_t hh, ll;
                    split2(va, vb, hh, ll);
                    *(uint32_t*)(Ch + rb + col) = hh;
                    *(uint32_t*)(Cl + rb + col) = ll;
                }
            }
        }
    }
}

// ================================================================
// Flash attention, pre-split bf16 inputs via cp.async, 2-stage ring.
// Grid (24 q-blocks of 128 rows, 64 bh). 256 threads = 8 warps.
// Stage: KH/KL/VH/VL each 64 x 144B. Output written bf16 hi/lo.
// ================================================================
#define APITCH 144
#define ASTG (4 * 64 * APITCH)     // 36864
#define AB_KH 0
#define AB_KL (64 * APITCH)
#define AB_VH (2 * 64 * APITCH)
#define AB_VL (3 * 64 * APITCH)
#define A_SMEM (2 * ASTG)          // 73728

__global__ void __launch_bounds__(256)
attn_mma(const __nv_bfloat16* __restrict__ Qh, const __nv_bfloat16* __restrict__ Ql,
         const __nv_bfloat16* __restrict__ Kh, const __nv_bfloat16* __restrict__ Kl,
         const __nv_bfloat16* __restrict__ Vh, const __nv_bfloat16* __restrict__ Vl,
         __nv_bfloat16* __restrict__ Oh, __nv_bfloat16* __restrict__ Ol) {
    extern __shared__ __align__(16) char sm[];
    const uint32_t sb = smem_u32(sm);

    const int tid  = threadIdx.x;
    const int lane = tid & 31;
    const int w    = tid >> 5;
    const int b    = blockIdx.y >> 4;
    const int h    = blockIdx.y & 15;
    const int q0   = blockIdx.x * 128;

    // ---- stage Q (128 rows hi+lo) into stage 0 via cp.async ----
    {
        const int row = tid >> 1;
        const int r6  = row & 63;
        const int isLo = tid & 1;
        const uint32_t buf = (row < 64) ? (isLo ? AB_KL : AB_KH)
                                        : (isLo ? AB_VL : AB_VH);
        const uint32_t dbase = sb + buf + (uint32_t)(r6 * APITCH);
        const __nv_bfloat16* srcq = (isLo ? Ql : Qh)
            + ((size_t)b * TT + q0 + row) * DD + h * HDIM;
#pragma unroll
        for (int j = 0; j < 8; j++) CP16(dbase + j * 16, srcq + j * 8);
        CP_COMMIT();
    }
    cp_wait<0>();
    __syncthreads();

    // ---- Q fragments (persist) ----
    uint32_t qfh[4][4], qfl[4][4];
    {
        const uint32_t bhi = (w < 4) ? AB_KH : AB_VH;
        const uint32_t blo = (w < 4) ? AB_KL : AB_VL;
        const uint32_t ao = (uint32_t)(((w * 16 + (lane & 15)) & 63) * APITCH
                                       + (lane >> 4) * 16);
#pragma unroll
        for (int ks = 0; ks < 4; ks++) {
            ldm4(qfh[ks], sb + bhi + ao + ks * 32);
            ldm4(qfl[ks], sb + blo + ao + ks * 32);
        }
    }
    __syncthreads();

    const int nkb = ((q0 + 127) / 3) / 64 + 1;   // <= 16

    auto issueKV = [&](int t) {
        const uint32_t st = sb + (uint32_t)(t & 1) * ASTG
                          + (uint32_t)((tid >> 2) * APITCH + (tid & 3) * 32);
        const size_t gro = ((size_t)b * TKK + t * 64 + (tid >> 2)) * DD
                         + h * HDIM + (tid & 3) * 16;
        CP16(st + AB_KH,      Kh + gro);
        CP16(st + AB_KH + 16, Kh + gro + 8);
        CP16(st + AB_KL,      Kl + gro);
        CP16(st + AB_KL + 16, Kl + gro + 8);
        CP16(st + AB_VH,      Vh + gro);
        CP16(st + AB_VH + 16, Vh + gro + 8);
        CP16(st + AB_VL,      Vl + gro);
        CP16(st + AB_VL + 16, Vl + gro + 8);
    };

    issueKV(0); CP_COMMIT();

    float oacc[8][4];
#pragma unroll
    for (int nt = 0; nt < 8; nt++)
#pragma unroll
        for (int t = 0; t < 4; t++) oacc[nt][t] = 0.f;
    float m0 = -1e30f, m1 = -1e30f, l0 = 0.f, l1 = 0.f;

    const uint32_t kfo = (uint32_t)((((lane >> 4) << 3) + (lane & 7)) * APITCH
                                    + ((lane >> 3) & 1) * 16);
    const uint32_t vfo = (uint32_t)(((((lane >> 3) & 1) * 8) + (lane & 7)) * APITCH
                                    + ((lane >> 4) & 1) * 16);
    const int rq = lane >> 2;
    const int cq = (lane & 3) * 2;
    const int qg0 = q0 + w * 16 + rq;
    const int qg1 = qg0 + 8;

    for (int t = 0; t < nkb; t++) {
        cp_wait<0>();
        __syncthreads();
        if (t + 1 < nkb) { issueKV(t + 1); CP_COMMIT(); }

        const uint32_t sbase = sb + (uint32_t)(t & 1) * ASTG;
        const int kbase = t * 64;

        // ---- S = Q K^T ----
        float sacc[8][4];
#pragma unroll
        for (int nt = 0; nt < 8; nt++)
#pragma unroll
            for (int tt = 0; tt < 4; tt++) sacc[nt][tt] = 0.f;

#pragma unroll
        for (int ks = 0; ks < 4; ks++) {
#pragma unroll
            for (int pi = 0; pi < 4; pi++) {
                uint32_t kh[4], kl[4];
                const uint32_t base = (uint32_t)(pi * 16 * APITCH) + kfo + ks * 32;
                ldm4(kh, sbase + AB_KH + base);
                ldm4(kl, sbase + AB_KL + base);
                mma16816(sacc[2 * pi],     qfh[ks], kh[0], kh[1]);
                mma16816(sacc[2 * pi],     qfh[ks], kl[0], kl[1]);
                mma16816(sacc[2 * pi],     qfl[ks], kh[0], kh[1]);
                mma16816(sacc[2 * pi + 1], qfh[ks], kh[2], kh[3]);
                mma16816(sacc[2 * pi + 1], qfh[ks], kl[2], kl[3]);
                mma16816(sacc[2 * pi + 1], qfl[ks], kh[2], kh[3]);
            }
        }

        // ---- mask + scale + online softmax ----
        float tm0 = -1e30f, tm1 = -1e30f;
#pragma unroll
        for (int nt = 0; nt < 8; nt++) {
            const int kg0 = kbase + nt * 8 + cq;
            const int kg1 = kg0 + 1;
            float s00 = (3 * kg0 <= qg0) ? sacc[nt][0] * 0.125f : -1e30f;
            float s01 = (3 * kg1 <= qg0) ? sacc[nt][1] * 0.125f : -1e30f;
            float s10 = (3 * kg0 <= qg1) ? sacc[nt][2] * 0.125f : -1e30f;
            float s11 = (3 * kg1 <= qg1) ? sacc[nt][3] * 0.125f : -1e30f;
            sacc[nt][0] = s00; sacc[nt][1] = s01;
            sacc[nt][2] = s10; sacc[nt][3] = s11;
            tm0 = fmaxf(tm0, fmaxf(s00, s01));
            tm1 = fmaxf(tm1, fmaxf(s10, s11));
        }
        tm0 = fmaxf(tm0, __shfl_xor_sync(0xffffffffu, tm0, 1));
        tm0 = fmaxf(tm0, __shfl_xor_sync(0xffffffffu, tm0, 2));
        tm1 = fmaxf(tm1, __shfl_xor_sync(0xffffffffu, tm1, 1));
        tm1 = fmaxf(tm1, __shfl_xor_sync(0xffffffffu, tm1, 2));

        const float mn0 = fmaxf(m0, tm0);
        const float mn1 = fmaxf(m1, tm1);
        const float al0 = __expf(m0 - mn0);
        const float al1 = __expf(m1 - mn1);
        float ps0 = 0.f, ps1 = 0.f;
#pragma unroll
        for (int nt = 0; nt < 8; nt++) {
            float p00 = __expf(sacc[nt][0] - mn0);
            float p01 = __expf(sacc[nt][1] - mn0);
            float p10 = __expf(sacc[nt][2] - mn1);
            float p11 = __expf(sacc[nt][3] - mn1);
            sacc[nt][0] = p00; sacc[nt][1] = p01;
            sacc[nt][2] = p10; sacc[nt][3] = p11;
            ps0 += p00 + p01;
            ps1 += p10 + p11;
        }
        ps0 += __shfl_xor_sync(0xffffffffu, ps0, 1);
        ps0 += __shfl_xor_sync(0xffffffffu, ps0, 2);
        ps1 += __shfl_xor_sync(0xffffffffu, ps1, 1);
        ps1 += __shfl_xor_sync(0xffffffffu, ps1, 2);
        l0 = l0 * al0 + ps0;
        l1 = l1 * al1 + ps1;
        m0 = mn0; m1 = mn1;

#pragma unroll
        for (int nt = 0; nt < 8; nt++) {
            oacc[nt][0] *= al0; oacc[nt][1] *= al0;
            oacc[nt][2] *= al1; oacc[nt][3] *= al1;
        }

        // ---- O += P V ----
#pragma unroll
        for (int ks = 0; ks < 4; ks++) {
            uint32_t pah[4], pal[4];
            split2(sacc[2 * ks][0],     sacc[2 * ks][1],     pah[0], pal[0]);
            split2(sacc[2 * ks][2],     sacc[2 * ks][3],     pah[1], pal[1]);
            split2(sacc[2 * ks + 1][0], sacc[2 * ks + 1][1], pah[2], pal[2]);
            split2(sacc[2 * ks + 1][2], sacc[2 * ks + 1][3], pah[3], pal[3]);
#pragma unroll
            for (int di = 0; di < 4; di++) {
                uint32_t vh[4], vl[4];
                const uint32_t base = (uint32_t)(ks * 16 * APITCH) + vfo + di * 32;
                ldm4t(vh, sbase + AB_VH + base);
                ldm4t(vl, sbase + AB_VL + base);
                mma16816(oacc[2 * di],     pah, vh[0], vh[1]);
                mma16816(oacc[2 * di],     pah, vl[0], vl[1]);
                mma16816(oacc[2 * di],     pal, vh[0], vh[1]);
                mma16816(oacc[2 * di + 1], pah, vh[2], vh[3]);
                mma16816(oacc[2 * di + 1], pah, vl[2], vl[3]);
                mma16816(oacc[2 * di + 1], pal, vh[2], vh[3]);
            }
        }
    }

    // ---- normalize + write hi/lo ----
    const float il0 = 1.0f / l0;
    const float il1 = 1.0f / l1;
    const size_t ob = ((size_t)b * TT + qg0) * DD + h * HDIM;
#pragma unroll
    for (int nt = 0; nt < 8; nt++) {
        const int col = nt * 8 + cq;
        uint32_t hh, ll;
        split2(oacc[nt][0] * il0, oacc[nt][1] * il0, hh, ll);
        *(uint32_t*)(Oh + ob + col) = hh;
        *(uint32_t*)(Ol + ob + col) = ll;
        split2(oacc[nt][2] * il1, oacc[nt][3] * il1, hh, ll);
        *(uint32_t*)(Oh + ob + (size_t)8 * DD + col) = hh;
        *(uint32_t*)(Ol + ob + (size_t)8 * DD + col) = ll;
    }
}

// ------------------------------------------------------------------
extern "C" void kernel_launch(void* const* d_in, const int* in_sizes, int n_in,
                              void* d_out, int out_size) {
    const float* x     = (const float*)d_in[0];
    const float* Wq    = (const float*)d_in[1];
    const float* Wk    = (const float*)d_in[2];
    const float* Wv    = (const float*)d_in[3];
    const float* Wo    = (const float*)d_in[4];
    const float* bo    = (const float*)d_in[5];
    const float* Wconv = (const float*)d_in[6];
    float* out = (float*)d_out;

    __nv_bfloat16 *xh, *xl, *wqh, *wql, *wkh, *wkl, *wvh, *wvl, *woh, *wol;
    __nv_bfloat16 *wth, *wtl, *kth, *ktl, *qh, *ql, *kh, *kl, *vh, *vl, *ah, *al;
    cudaGetSymbolAddress((void**)&xh,  g_xh);  cudaGetSymbolAddress((void**)&xl,  g_xl);
    cudaGetSymbolAddress((void**)&wqh, g_wqh); cudaGetSymbolAddress((void**)&wql, g_wql);
    cudaGetSymbolAddress((void**)&wkh, g_wkh); cudaGetSymbolAddress((void**)&wkl, g_wkl);
    cudaGetSymbolAddress((void**)&wvh, g_wvh); cudaGetSymbolAddress((void**)&wvl, g_wvl);
    cudaGetSymbolAddress((void**)&woh, g_woh); cudaGetSymbolAddress((void**)&wol, g_wol);
    cudaGetSymbolAddress((void**)&wth, g_wth); cudaGetSymbolAddress((void**)&wtl, g_wtl);
    cudaGetSymbolAddress((void**)&kth, g_kth); cudaGetSymbolAddress((void**)&ktl, g_ktl);
    cudaGetSymbolAddress((void**)&qh,  g_qh);  cudaGetSymbolAddress((void**)&ql,  g_ql);
    cudaGetSymbolAddress((void**)&kh,  g_kh);  cudaGetSymbolAddress((void**)&kl,  g_kl);
    cudaGetSymbolAddress((void**)&vh,  g_vh);  cudaGetSymbolAddress((void**)&vl,  g_vl);
    cudaGetSymbolAddress((void**)&ah,  g_ah);  cudaGetSymbolAddress((void**)&al,  g_al);

    cudaFuncSetAttribute(mma_gemm<0>, cudaFuncAttributeMaxDynamicSharedMemorySize, G_SMEM);
    cudaFuncSetAttribute(mma_gemm<1>, cudaFuncAttributeMaxDynamicSharedMemorySize, G_SMEM);
    cudaFuncSetAttribute(mma_gemm<2>, cudaFuncAttributeMaxDynamicSharedMemorySize, G_SMEM);
    cudaFuncSetAttribute(attn_mma,    cudaFuncAttributeMaxDynamicSharedMemorySize, A_SMEM);

    // ---- conversions ----
    split8_arr<<<(NX / 8 + 255) / 256, 256>>>(x, xh, xl, NX);
    split8_arr<<<(NW / 8 + 255) / 256, 256>>>(Wq, wqh, wql, NW);
    split8_arr<<<(NW / 8 + 255) / 256, 256>>>(Wk, wkh, wkl, NW);
    split8_arr<<<(NW / 8 + 255) / 256, 256>>>(Wv, wvh, wvl, NW);
    split8_arr<<<(NW / 8 + 255) / 256, 256>>>(Wo, woh, wol, NW);
    conv_w_split<<<(NWT + 255) / 256, 256>>>(Wconv, wth, wtl);
    first_rows<<<16, 256>>>(xh, xl, kth, ktl);

    // ---- GEMMs ----
    mma_gemm<1><<<dim3(8, 32), 512, G_SMEM>>>(xh, xl, wth, wtl, nullptr,
                                              kth, ktl, 4096, 1024, 3072);
    mma_gemm<0><<<dim3(8, 96), 512, G_SMEM>>>(xh, xl, wqh, wql, nullptr,
                                              qh, ql, BB * TT, 1024, 1024);
    mma_gemm<0><<<dim3(8, 33), 512, G_SMEM>>>(kth, ktl, wkh, wkl, nullptr,
                                              kh, kl, BB * TKK, 1024, 1024);
    mma_gemm<0><<<dim3(8, 33), 512, G_SMEM>>>(kth, ktl, wvh, wvl, nullptr,
                                              vh, vl, BB * TKK, 1024, 1024);

    // ---- attention ----
    attn_mma<<<dim3(24, 64), 256, A_SMEM>>>(qh, ql, kh, kl, vh, vl, ah, al);

    // ---- output projection ----
    mma_gemm<2><<<dim3(8, 96), 512, G_SMEM>>>(ah, al, woh, wol, bo,
                                              out, nullptr, BB * TT, 1024, 1024);
}